// round 11
// baseline (speedup 1.0000x reference)
#include <cuda_runtime.h>
#include <cuda_bf16.h>
#include <math.h>
#include <stdint.h>

// Problem constants
#define B    32
#define P    197
#define ENC  768
#define EMB  512
#define HID  512
#define ATT  256
#define VOCAB 32000
#define SLEN 41
#define T    40
#define N4H  2048          // 4*HID
#define NCAT 3072          // ATT + ENC + 4*HID
#define NROWS (T*B)        // 1280
#define KSPLIT 1536        // 3 * HID  (split-bf16 K)

#define NCTA 128
#define NTHR 256

// skewed staging strides (>= row footprint, ≡1 mod 32 for bank spread)
#define STRA 641
#define STRC 897
#define STRG 17            // gates staging stride

// ---------------- device scratch (no allocs allowed) ----------------
__device__ float g_h0[B*HID];
__device__ float g_cbuf[2][B*HID];
__device__ float g_att1T[B*ATT*P];      // [b][a][p]
__device__ float g_Xproj[NROWS*N4H];
__device__ float g_y[B*NCAT];
__device__ float g_awe[B*ENC];
__device__ float g_H[NROWS*HID];        // h rows, row = t*32 + b
__device__ __nv_bfloat16 g_Abf[NROWS*KSPLIT];         // [m][k'] = [Hh|Hl|Hh]
__device__ __nv_bfloat16 g_Bbf[(size_t)VOCAB*KSPLIT]; // [n][k'] = [Wh|Wh|Wl]

// global barrier state (zero-initialized; returns to this state every launch)
__device__ unsigned int g_cnt2[2];
__device__ volatile unsigned int g_flag2[2];

__device__ __forceinline__ float sigm(float x) { return 1.f / (1.f + __expf(-x)); }

__device__ __forceinline__ uint32_t smem_u32(const void* p) {
    uint32_t a;
    asm("{ .reg .u64 t; cvta.to.shared.u64 t, %1; cvt.u32.u64 %0, t; }" : "=r"(a) : "l"(p));
    return a;
}
#define SW128(off) ((off) ^ (((off) >> 3) & 0x70))

#define CP_ASYNC16(dst, src) asm volatile("cp.async.cg.shared.global [%0], [%1], 16;" :: "r"(dst), "l"(src))
#define CP_COMMIT()          asm volatile("cp.async.commit_group;" ::: "memory")
#define CP_WAIT2()           asm volatile("cp.async.wait_group 2;" ::: "memory")
#define CP_WAIT0()           asm volatile("cp.async.wait_group 0;" ::: "memory")

#define LDSM_X4(r0, r1, r2, r3, addr) \
    asm volatile("ldmatrix.sync.aligned.m8n8.x4.shared.b16 {%0,%1,%2,%3}, [%4];" \
        : "=r"(r0), "=r"(r1), "=r"(r2), "=r"(r3) : "r"(addr))

#define MMA16816(d, a, b0, b1) \
    asm volatile("mma.sync.aligned.m16n8k16.row.col.f32.bf16.bf16.f32 " \
        "{%0,%1,%2,%3}, {%4,%5,%6,%7}, {%8,%9}, {%0,%1,%2,%3};" \
        : "+f"((d)[0]), "+f"((d)[1]), "+f"((d)[2]), "+f"((d)[3]) \
        : "r"((a)[0]), "r"((a)[1]), "r"((a)[2]), "r"((a)[3]), "r"(b0), "r"(b1))

// grid-wide barrier (even count per launch -> replay-safe)
__device__ __forceinline__ void gbar(int slot) {
    __syncthreads();
    if (threadIdx.x == 0) {
        __threadfence();
        unsigned int old = atomicAdd(&g_cnt2[slot], 1u);
        if (old == NCTA - 1) {
            g_cnt2[slot] = 0;
            g_flag2[slot ^ 1] = 0;
            __threadfence();
            g_flag2[slot] = 1;
        } else {
            while (g_flag2[slot] == 0) { }
        }
        __threadfence();
    }
    __syncthreads();
}

// ---------------- setup kernels ----------------
// fused mean + h0/c0 init. grid B, 512 threads.
__global__ void __launch_bounds__(512) k_init(const float* __restrict__ enc,
                                              const float* __restrict__ W_inh,
                                              const float* __restrict__ b_inh,
                                              const float* __restrict__ W_inc,
                                              const float* __restrict__ b_inc) {
    __shared__ float sm[ENC];
    int b = blockIdx.x;
    for (int d = threadIdx.x; d < ENC; d += 512) {
        const float* p = enc + (size_t)b * P * ENC + d;
        float s = 0.f;
        #pragma unroll 8
        for (int pp = 0; pp < P; pp++) s += p[pp * ENC];
        sm[d] = s * (1.f / (float)P);
    }
    __syncthreads();
    int n = threadIdx.x;
    float ah = b_inh[n], ac = b_inc[n];
    #pragma unroll 8
    for (int k = 0; k < ENC; k++) {
        float m = sm[k];
        ah = fmaf(m, W_inh[k*HID + n], ah);
        ac = fmaf(m, W_inc[k*HID + n], ac);
    }
    g_h0[b*HID + n] = ah;
    g_cbuf[0][b*HID + n] = ac;
}

__global__ void __launch_bounds__(256) k_att1T(const float* __restrict__ enc,
                                               const float* __restrict__ W_ea,
                                               const float* __restrict__ b_ea) {
    __shared__ __align__(16) float sx[16 * ENC];
    int row0 = blockIdx.x * 16;
    for (int idx = threadIdx.x; idx < 16 * ENC; idx += blockDim.x)
        sx[idx] = enc[(size_t)row0 * ENC + idx];
    __syncthreads();
    int a = threadIdx.x;
    float acc[16];
    float bias = b_ea[a];
    #pragma unroll
    for (int r = 0; r < 16; r++) acc[r] = bias;
    #pragma unroll 2
    for (int k = 0; k < ENC; k += 4) {
        float w0 = W_ea[k*ATT + a];
        float w1 = W_ea[(k+1)*ATT + a];
        float w2 = W_ea[(k+2)*ATT + a];
        float w3 = W_ea[(k+3)*ATT + a];
        #pragma unroll
        for (int r = 0; r < 16; r++) {
            float4 xv = *(const float4*)&sx[r*ENC + k];
            acc[r] = fmaf(xv.x, w0, acc[r]);
            acc[r] = fmaf(xv.y, w1, acc[r]);
            acc[r] = fmaf(xv.z, w2, acc[r]);
            acc[r] = fmaf(xv.w, w3, acc[r]);
        }
    }
    #pragma unroll
    for (int r = 0; r < 16; r++) {
        int gr = row0 + r;
        int b = gr / P, p = gr - b * P;
        g_att1T[((size_t)b*ATT + a)*P + p] = acc[r];
    }
}

__global__ void __launch_bounds__(256) k_xproj(const int* __restrict__ captions,
                                               const float* __restrict__ emb,
                                               const float* __restrict__ W_ih,
                                               const float* __restrict__ b_ih,
                                               const float* __restrict__ b_hh) {
    __shared__ __align__(16) float sx[16 * EMB];
    int row0 = blockIdx.y * 16;
    for (int idx = threadIdx.x; idx < 16 * EMB; idx += blockDim.x) {
        int r = idx >> 9, k = idx & 511;
        int gr = row0 + r;
        int t = gr >> 5, b = gr & 31;
        int tok = captions[b*SLEN + t];
        sx[idx] = emb[(size_t)tok * EMB + k];
    }
    __syncthreads();
    int n = blockIdx.x * 256 + threadIdx.x;
    float acc[16];
    float bias = b_ih[n] + b_hh[n];
    #pragma unroll
    for (int r = 0; r < 16; r++) acc[r] = bias;
    #pragma unroll 2
    for (int k = 0; k < EMB; k += 4) {
        float w0 = W_ih[(size_t)k*N4H + n];
        float w1 = W_ih[(size_t)(k+1)*N4H + n];
        float w2 = W_ih[(size_t)(k+2)*N4H + n];
        float w3 = W_ih[(size_t)(k+3)*N4H + n];
        #pragma unroll
        for (int r = 0; r < 16; r++) {
            float4 xv = *(const float4*)&sx[r*EMB + k];
            acc[r] = fmaf(xv.x, w0, acc[r]);
            acc[r] = fmaf(xv.y, w1, acc[r]);
            acc[r] = fmaf(xv.z, w2, acc[r]);
            acc[r] = fmaf(xv.w, w3, acc[r]);
        }
    }
    #pragma unroll
    for (int r = 0; r < 16; r++)
        g_Xproj[(size_t)(row0 + r)*N4H + n] = acc[r];
}

// ---------------- persistent fused recurrent loop (R8 version) ----------------
#define SMEM_LOOP_FLOATS 55168
#define SMEM_LOOP_BYTES  (SMEM_LOOP_FLOATS * 4)

__global__ void __launch_bounds__(NTHR) k_loop(const float* __restrict__ enc,
                                               const float* __restrict__ w_fa,
                                               const float* __restrict__ b_fa,
                                               const float* __restrict__ W_ih,
                                               const float* __restrict__ W_da,
                                               const float* __restrict__ W_fb,
                                               const float* __restrict__ W_hh,
                                               const float* __restrict__ b_da,
                                               const float* __restrict__ b_fb) {
    extern __shared__ float smx[];
    float* sW   = smx;
    float* sWi  = smx + 12416;
    float* sbuf = smx + 24832;
    float* sAtt = smx + 53536;
    float* sbc  = smx + 54560;
    float* sg   = smx + 54592;

    int tid  = threadIdx.x;
    int cta  = blockIdx.x;
    int lane = tid & 31, warp = tid >> 5;
    int rg = lane & 7, ks = lane >> 3;

    // ---- one-time preload of weight slices (gather straight from inputs) ----
    {
        int cb24 = cta * 24;
        for (int e = tid; e < 512 * 24; e += NTHR) {
            int k = e / 24, c = e - k * 24;
            int n = cb24 + c;
            float v;
            if (n < ATT)            v = W_da[k*ATT + n];
            else if (n < ATT+ENC)   v = W_fb[k*ENC + (n - ATT)];
            else                    v = W_hh[k*N4H + (n - ATT - ENC)];
            sW[k*24 + c + 40*(k >> 7)] = v;
        }
        // quadrant-folded Wih columns: logical col c -> global col (c>>2)*512 + cta*4 + (c&3)
        for (int e = tid; e < 768 * 16; e += NTHR) {
            int k = e >> 4, c = e & 15;
            int gc = (c >> 2) * 512 + cta * 4 + (c & 3);
            sWi[k*16 + c + 40*(k / 192)] = W_ih[(size_t)(EMB + k)*N4H + gc];
        }
        if (tid < 24) {
            int n = cta * 24 + tid;
            sbc[tid] = (n < ATT) ? b_da[n] : ((n < ATT+ENC) ? b_fb[n - ATT] : 0.f);
        }
    }
    __syncthreads();

    int bs = 0;
    for (int t = 0; t < T; t++) {
        // ===== Phase A: y = h @ Wcat + bcat (all CTAs, 24 cols each) =====
        {
            const float* hsrc = (t == 0) ? g_h0 : (g_H + (size_t)(t-1)*B*HID);
            #pragma unroll 4
            for (int r = 0; r < 32; r++) {
                int k0 = tid, k1 = tid + 256;
                sbuf[r*STRA + k0 + 40*(k0 >> 7)] = hsrc[r*512 + k0];
                sbuf[r*STRA + k1 + 40*(k1 >> 7)] = hsrc[r*512 + k1];
            }
            __syncthreads();
            float acc[12];
            #pragma unroll
            for (int x = 0; x < 12; x++) acc[x] = 0.f;
            int c0 = warp * 3;
            const float* hb = sbuf + 128*ks + 40*ks;
            const float* wb = sW + (128*ks)*24 + c0 + 40*ks;
            #pragma unroll 4
            for (int kl = 0; kl < 128; kl++) {
                float w0 = wb[kl*24 + 0];
                float w1 = wb[kl*24 + 1];
                float w2 = wb[kl*24 + 2];
                #pragma unroll
                for (int i = 0; i < 4; i++) {
                    float h = hb[(rg + 8*i)*STRA + kl];
                    acc[i*3+0] = fmaf(h, w0, acc[i*3+0]);
                    acc[i*3+1] = fmaf(h, w1, acc[i*3+1]);
                    acc[i*3+2] = fmaf(h, w2, acc[i*3+2]);
                }
            }
            #pragma unroll
            for (int x = 0; x < 12; x++) {
                acc[x] += __shfl_xor_sync(0xffffffffu, acc[x], 8);
                acc[x] += __shfl_xor_sync(0xffffffffu, acc[x], 16);
            }
            if (ks == 0) {
                #pragma unroll
                for (int i = 0; i < 4; i++) {
                    int row = rg + 8*i;
                    #pragma unroll
                    for (int j = 0; j < 3; j++)
                        g_y[row*NCAT + cta*24 + c0 + j] = acc[i*3+j] + sbc[c0 + j];
                }
            }
            __syncthreads();
        }
        gbar(bs); bs ^= 1;

        // ===== Phase B: attention (CTAs 0..31, one batch each) =====
        if (cta < 32) {
            int b = cta;
            float* s_att2  = sAtt;
            float* s_wfa   = sAtt + 256;
            float* s_red   = sAtt + 512;
            float* s_alpha = sAtt + 768;
            s_att2[tid] = g_y[b*NCAT + tid];
            s_wfa[tid]  = w_fa[tid];
            __syncthreads();

            float ev = -1e30f;
            if (tid < P) {
                float a0 = b_fa[0];
                const float* at = g_att1T + (size_t)(b*ATT)*P + tid;
                #pragma unroll 16
                for (int a = 0; a < ATT; a++) {
                    float v = at[(size_t)a*P] + s_att2[a];
                    a0 = fmaf(fmaxf(v, 0.f), s_wfa[a], a0);
                }
                ev = a0;
            }
            s_red[tid] = ev; __syncthreads();
            for (int s = 128; s > 0; s >>= 1) {
                if (tid < s) s_red[tid] = fmaxf(s_red[tid], s_red[tid + s]);
                __syncthreads();
            }
            float mx = s_red[0];
            __syncthreads();
            float ex = (tid < P) ? __expf(ev - mx) : 0.f;
            s_red[tid] = ex; __syncthreads();
            for (int s = 128; s > 0; s >>= 1) {
                if (tid < s) s_red[tid] += s_red[tid + s];
                __syncthreads();
            }
            float inv = 1.f / s_red[0];
            s_alpha[tid] = ex * inv;
            __syncthreads();

            float a0 = 0.f, a1 = 0.f, a2 = 0.f;
            const float* ep = enc + (size_t)b * P * ENC + tid;
            #pragma unroll 4
            for (int p = 0; p < P; p++) {
                float al = s_alpha[p];
                const float* rowp = ep + (size_t)p * ENC;
                a0 = fmaf(al, rowp[0],   a0);
                a1 = fmaf(al, rowp[256], a1);
                a2 = fmaf(al, rowp[512], a2);
            }
            g_awe[b*ENC + tid]       = sigm(g_y[b*NCAT + ATT + tid])       * a0;
            g_awe[b*ENC + 256 + tid] = sigm(g_y[b*NCAT + ATT + 256 + tid]) * a1;
            g_awe[b*ENC + 512 + tid] = sigm(g_y[b*NCAT + ATT + 512 + tid]) * a2;
        }
        gbar(bs); bs ^= 1;

        // ===== Phase C+D: gates GEMM (quadrant-folded cols) + LSTM pointwise =====
        {
            #pragma unroll 2
            for (int r = 0; r < 32; r++) {
                #pragma unroll
                for (int q = 0; q < 3; q++) {
                    int k = tid + q * 256;
                    sbuf[r*STRC + k + 40*(k / 192)] = g_awe[r*768 + k];
                }
            }
            __syncthreads();
            float acc[8];
            #pragma unroll
            for (int x = 0; x < 8; x++) acc[x] = 0.f;
            int c0 = warp * 2;
            const float* ab = sbuf + 192*ks + 40*ks;
            const float* wb = sWi + (192*ks)*16 + c0 + 40*ks;
            #pragma unroll 4
            for (int kl = 0; kl < 192; kl++) {
                float w0 = wb[kl*16 + 0];
                float w1 = wb[kl*16 + 1];
                #pragma unroll
                for (int i = 0; i < 4; i++) {
                    float a = ab[(rg + 8*i)*STRC + kl];
                    acc[i*2+0] = fmaf(a, w0, acc[i*2+0]);
                    acc[i*2+1] = fmaf(a, w1, acc[i*2+1]);
                }
            }
            #pragma unroll
            for (int x = 0; x < 8; x++) {
                acc[x] += __shfl_xor_sync(0xffffffffu, acc[x], 8);
                acc[x] += __shfl_xor_sync(0xffffffffu, acc[x], 16);
            }
            if (ks == 0) {
                #pragma unroll
                for (int i = 0; i < 4; i++) {
                    int row = rg + 8*i;
                    #pragma unroll
                    for (int j = 0; j < 2; j++) {
                        int lc = c0 + j;
                        int gc = (lc >> 2) * 512 + cta * 4 + (lc & 3);
                        sg[row*STRG + lc] = acc[i*2+j]
                            + g_Xproj[(size_t)(t*B + row)*N4H + gc]
                            + g_y[row*NCAT + 1024 + gc];
                    }
                }
            }
            __syncthreads();
            // Phase D folded in: this CTA owns u = cta*4 + 0..3 for all 32 rows
            if (tid < 128) {
                int row = tid >> 2, off = tid & 3;
                int u = cta * 4 + off;
                float gi = sg[row*STRG + off];
                float gf = sg[row*STRG + 4 + off];
                float gg = sg[row*STRG + 8 + off];
                float go = sg[row*STRG + 12 + off];
                float cp = g_cbuf[t & 1][row*512 + u];
                float cn = sigm(gf) * cp + sigm(gi) * tanhf(gg);
                float hn = sigm(go) * tanhf(cn);
                g_cbuf[(t + 1) & 1][row*512 + u] = cn;
                g_H[(size_t)t * B * HID + row*512 + u] = hn;
            }
            __syncthreads();
        }
        gbar(bs); bs ^= 1;
    }
    // 3 barriers * 40 steps = 120 (even) -> replay-safe
}

// ---------------- bf16 split conversions ----------------
__global__ void k_convA() {
    int i = blockIdx.x * 256 + threadIdx.x;
    if (i >= NROWS * HID) return;
    int m = i >> 9, k = i & 511;
    float x = g_H[i];
    __nv_bfloat16 hb = __float2bfloat16(x);
    __nv_bfloat16 lb = __float2bfloat16(x - __bfloat162float(hb));
    __nv_bfloat16* row = g_Abf + (size_t)m * KSPLIT;
    row[k] = hb;
    row[512 + k] = lb;
    row[1024 + k] = hb;
}

__global__ void k_convB(const float* __restrict__ W_out) {
    __shared__ float tile[32][33];
    int n0 = blockIdx.x * 32;
    int k0 = blockIdx.y * 32;
    int tn = threadIdx.x & 31, tr = threadIdx.x >> 5;
    #pragma unroll
    for (int r = 0; r < 4; r++) {
        int k = k0 + tr + r * 8;
        tile[tr + r * 8][tn] = W_out[(size_t)k * VOCAB + n0 + tn];
    }
    __syncthreads();
    #pragma unroll
    for (int r = 0; r < 4; r++) {
        int n = n0 + tr + r * 8;
        float x = tile[tn][tr + r * 8];
        __nv_bfloat16 hb = __float2bfloat16(x);
        __nv_bfloat16 lb = __float2bfloat16(x - __bfloat162float(hb));
        __nv_bfloat16* row = g_Bbf + (size_t)n * KSPLIT;
        row[k0 + tn] = hb;
        row[512 + k0 + tn] = hb;
        row[1024 + k0 + tn] = lb;
    }
}

// ---------------- mma.sync output GEMM: 4-stage, single-sync, MMA-first issue ----------------
#define NT 24             // k-tiles (1536/64)
#define NSTAGE 4
#define STAGE_BYTES 32768 // A 16KB + B 16KB per stage

__device__ __forceinline__ void gemm_load_tile(uint32_t sA,
                                               const __nv_bfloat16* gA,
                                               const __nv_bfloat16* gB, int tid) {
    uint32_t sB = sA + 16384;
    #pragma unroll
    for (int i = 0; i < 4; i++) {
        int chunk = tid + i * 256;          // 0..1023
        int r = chunk >> 3, c = chunk & 7;
        CP_ASYNC16(sA + SW128(r * 128 + c * 16),
                   (const char*)gA + (size_t)r * KSPLIT * 2 + c * 16);
    }
    #pragma unroll
    for (int i = 0; i < 4; i++) {
        int chunk = tid + i * 256;
        int r = chunk >> 3, c = chunk & 7;
        CP_ASYNC16(sB + SW128(r * 128 + c * 16),
                   (const char*)gB + (size_t)r * KSPLIT * 2 + c * 16);
    }
}

__global__ void __launch_bounds__(256) k_out_mma(const float* __restrict__ b_out,
                                                 float* __restrict__ out) {
    extern __shared__ char dsm[];
    uint32_t raw = smem_u32(dsm);
    uint32_t base = (raw + 1023) & ~1023u;

    int tid = threadIdx.x;
    int lane = tid & 31, wid = tid >> 5;
    int wm = wid & 1;
    int wn = wid >> 1;

    int row0 = blockIdx.x * 128;
    int n0   = blockIdx.y * 128;

    const __nv_bfloat16* gA0 = g_Abf + (size_t)row0 * KSPLIT;
    const __nv_bfloat16* gB0 = g_Bbf + (size_t)n0 * KSPLIT;

    int rowA = wm * 64 + (lane & 15);
    int koffA = (lane >> 4) << 4;
    int rowB = wn * 32 + (lane & 7) + ((lane >> 4) << 3);
    int koffB = ((lane >> 3) & 1) << 4;

    float acc[4][4][4];
    #pragma unroll
    for (int f = 0; f < 4; f++)
        #pragma unroll
        for (int j = 0; j < 4; j++)
            #pragma unroll
            for (int e = 0; e < 4; e++) acc[f][j][e] = 0.f;

    // prologue: 3 tiles committed
    #pragma unroll
    for (int kt = 0; kt < 3; kt++) {
        gemm_load_tile(base + kt * STAGE_BYTES, gA0 + kt * 64, gB0 + kt * 64, tid);
        CP_COMMIT();
    }

    for (int kt = 0; kt < NT; kt++) {
        // pending: tiles kt, kt+1, kt+2 -> wait to <=2 pending => tile kt landed
        CP_WAIT2();
        __syncthreads();   // tile kt visible; all warps done reading buf (kt-1)%4
        uint32_t sA = base + (kt % NSTAGE) * STAGE_BYTES;
        uint32_t sB = sA + 16384;

        // ---- kss = 0 quarter first: saturate tensor pipe before issuing loads ----
        {
            uint32_t a[4][4];
            #pragma unroll
            for (int f = 0; f < 4; f++)
                LDSM_X4(a[f][0], a[f][1], a[f][2], a[f][3],
                        sA + SW128((rowA + f * 16) * 128 + koffA));
            uint32_t bfr[2][4];
            #pragma unroll
            for (int g = 0; g < 2; g++)
                LDSM_X4(bfr[g][0], bfr[g][1], bfr[g][2], bfr[g][3],
                        sB + SW128((rowB + g * 16) * 128 + koffB));
            #pragma unroll
            for (int f = 0; f < 4; f++)
                #pragma unroll
                for (int j = 0; j < 4; j++)
                    MMA16816(acc[f][j], a[f],
                             bfr[j >> 1][(j & 1) * 2], bfr[j >> 1][(j & 1) * 2 + 1]);
        }

        // ---- prefetch tile kt+3 into buf (kt+3)%4 == (kt-1)%4 (safe post-barrier) ----
        if (kt + 3 < NT) {
            gemm_load_tile(base + ((kt + 3) % NSTAGE) * STAGE_BYTES,
                           gA0 + (size_t)(kt + 3) * 64, gB0 + (size_t)(kt + 3) * 64, tid);
            CP_COMMIT();
        }

        // ---- remaining kss = 1..3 ----
        #pragma unroll
        for (int kss = 1; kss < 4; kss++) {
            uint32_t a[4][4];
            #pragma unroll
            for (int f = 0; f < 4; f++)
                LDSM_X4(a[f][0], a[f][1], a[f][2], a[f][3],
                        sA + SW128((rowA + f * 16) * 128 + kss * 32 + koffA));
            uint32_t bfr[2][4];
            #pragma unroll
            for (int g = 0; g < 2; g++)
                LDSM_X4(bfr[g][0], bfr[g][1], bfr[g][2], bfr[g][3],
                        sB + SW128((rowB + g * 16) * 128 + kss * 32 + koffB));
            #pragma unroll
            for (int f = 0; f < 4; f++)
                #pragma unroll
                for (int j = 0; j < 4; j++)
                    MMA16816(acc[f][j], a[f],
                             bfr[j >> 1][(j & 1) * 2], bfr[j >> 1][(j & 1) * 2 + 1]);
        }
    }
    CP_WAIT0();

    #pragma unroll
    for (int j = 0; j < 4; j++) {
        int n = n0 + wn * 32 + j * 8 + (lane & 3) * 2;
        float bo0 = b_out[n], bo1 = b_out[n + 1];
        #pragma unroll
        for (int f = 0; f < 4; f++) {
            int rl = wm * 64 + f * 16 + (lane >> 2);
            #pragma unroll
            for (int half = 0; half < 2; half++) {
                int grow = row0 + rl + half * 8;
                int bb = grow & 31, tt = grow >> 5;
                float2 v = make_float2(acc[f][j][half * 2] + bo0,
                                       acc[f][j][half * 2 + 1] + bo1);
                *(float2*)(out + ((size_t)bb * T + tt) * VOCAB + n) = v;
            }
        }
    }
}

// ---------------- launch ----------------
extern "C" void kernel_launch(void* const* d_in, const int* in_sizes, int n_in,
                              void* d_out, int out_size) {
    const float* enc    = (const float*)d_in[0];
    const int*   caps   = (const int*)  d_in[1];
    const float* emb    = (const float*)d_in[2];
    const float* W_ea   = (const float*)d_in[3];
    const float* b_ea   = (const float*)d_in[4];
    const float* W_da   = (const float*)d_in[5];
    const float* b_da   = (const float*)d_in[6];
    const float* w_fa   = (const float*)d_in[7];
    const float* b_fa   = (const float*)d_in[8];
    const float* W_inh  = (const float*)d_in[9];
    const float* b_inh  = (const float*)d_in[10];
    const float* W_inc  = (const float*)d_in[11];
    const float* b_inc  = (const float*)d_in[12];
    const float* W_fb   = (const float*)d_in[13];
    const float* b_fb   = (const float*)d_in[14];
    const float* W_ih   = (const float*)d_in[15];
    const float* b_ih   = (const float*)d_in[16];
    const float* W_hh   = (const float*)d_in[17];
    const float* b_hh   = (const float*)d_in[18];
    const float* W_out  = (const float*)d_in[19];
    const float* b_out  = (const float*)d_in[20];
    float* out = (float*)d_out;

    cudaFuncSetAttribute(k_out_mma, cudaFuncAttributeMaxDynamicSharedMemorySize,
                         NSTAGE * STAGE_BYTES + 1024);
    cudaFuncSetAttribute(k_loop, cudaFuncAttributeMaxDynamicSharedMemorySize,
                         SMEM_LOOP_BYTES);

    k_init<<<B, 512>>>(enc, W_inh, b_inh, W_inc, b_inc);
    k_att1T<<<(B*P)/16, 256>>>(enc, W_ea, b_ea);
    k_xproj<<<dim3(N4H/256, NROWS/16), 256>>>(caps, emb, W_ih, b_ih, b_hh);
    k_loop<<<NCTA, NTHR, SMEM_LOOP_BYTES>>>(enc, w_fa, b_fa, W_ih,
                                            W_da, W_fb, W_hh, b_da, b_fb);
    k_convA<<<(NROWS*HID + 255)/256, 256>>>();
    k_convB<<<dim3(VOCAB/32, HID/32), 256>>>(W_out);
    k_out_mma<<<dim3(NROWS/128, VOCAB/128), 256, NSTAGE*STAGE_BYTES + 1024>>>(b_out, out);
}

// round 12
// speedup vs baseline: 1.0515x; 1.0515x over previous
#include <cuda_runtime.h>
#include <cuda_bf16.h>
#include <math.h>
#include <stdint.h>

// Problem constants
#define B    32
#define P    197
#define ENC  768
#define EMB  512
#define HID  512
#define ATT  256
#define VOCAB 32000
#define SLEN 41
#define T    40
#define N4H  2048          // 4*HID
#define NCAT 3072          // ATT + ENC + 4*HID
#define NROWS (T*B)        // 1280
#define KSPLIT 1536        // 3 * HID  (split-bf16 K)

#define NCTA 128
#define NTHR 256

// skewed staging strides (>= row footprint, ≡1 mod 32 for bank spread)
#define STRA 641
#define STRC 897
#define STRG 17            // gates staging stride

// ---------------- device scratch (no allocs allowed) ----------------
__device__ float g_h0[B*HID];
__device__ float g_cbuf[2][B*HID];
__device__ float g_att1T[B*ATT*P];      // [b][a][p]
__device__ float g_Xproj[NROWS*N4H];
__device__ float g_y[B*NCAT];
__device__ float g_awe[B*ENC];
__device__ float g_H[NROWS*HID];        // h rows, row = t*32 + b
__device__ __nv_bfloat16 g_Abf[NROWS*KSPLIT];         // [m][k'] = [Hh|Hl|Hh]
__device__ __nv_bfloat16 g_Bbf[(size_t)VOCAB*KSPLIT]; // [n][k'] = [Wh|Wh|Wl]

// global barrier state (zero-initialized; returns to this state every launch)
__device__ unsigned int g_cnt2[2];
__device__ volatile unsigned int g_flag2[2];

__device__ __forceinline__ float sigm(float x) { return 1.f / (1.f + __expf(-x)); }

__device__ __forceinline__ uint32_t smem_u32(const void* p) {
    uint32_t a;
    asm("{ .reg .u64 t; cvta.to.shared.u64 t, %1; cvt.u32.u64 %0, t; }" : "=r"(a) : "l"(p));
    return a;
}
#define SW128(off) ((off) ^ (((off) >> 3) & 0x70))

#define CP_ASYNC16(dst, src) asm volatile("cp.async.cg.shared.global [%0], [%1], 16;" :: "r"(dst), "l"(src))
#define CP_COMMIT()          asm volatile("cp.async.commit_group;" ::: "memory")
#define CP_WAIT2()           asm volatile("cp.async.wait_group 2;" ::: "memory")
#define CP_WAIT0()           asm volatile("cp.async.wait_group 0;" ::: "memory")

#define LDSM_X4(r0, r1, r2, r3, addr) \
    asm volatile("ldmatrix.sync.aligned.m8n8.x4.shared.b16 {%0,%1,%2,%3}, [%4];" \
        : "=r"(r0), "=r"(r1), "=r"(r2), "=r"(r3) : "r"(addr))

#define MMA16816(d, a, b0, b1) \
    asm volatile("mma.sync.aligned.m16n8k16.row.col.f32.bf16.bf16.f32 " \
        "{%0,%1,%2,%3}, {%4,%5,%6,%7}, {%8,%9}, {%0,%1,%2,%3};" \
        : "+f"((d)[0]), "+f"((d)[1]), "+f"((d)[2]), "+f"((d)[3]) \
        : "r"((a)[0]), "r"((a)[1]), "r"((a)[2]), "r"((a)[3]), "r"(b0), "r"(b1))

// grid-wide barrier (even count per launch -> replay-safe)
__device__ __forceinline__ void gbar(int slot) {
    __syncthreads();
    if (threadIdx.x == 0) {
        __threadfence();
        unsigned int old = atomicAdd(&g_cnt2[slot], 1u);
        if (old == NCTA - 1) {
            g_cnt2[slot] = 0;
            g_flag2[slot ^ 1] = 0;
            __threadfence();
            g_flag2[slot] = 1;
        } else {
            while (g_flag2[slot] == 0) { }
        }
        __threadfence();
    }
    __syncthreads();
}

// ---------------- setup kernels ----------------
// fused mean + h0/c0 init. grid B, 512 threads.
__global__ void __launch_bounds__(512) k_init(const float* __restrict__ enc,
                                              const float* __restrict__ W_inh,
                                              const float* __restrict__ b_inh,
                                              const float* __restrict__ W_inc,
                                              const float* __restrict__ b_inc) {
    __shared__ float sm[ENC];
    int b = blockIdx.x;
    for (int d = threadIdx.x; d < ENC; d += 512) {
        const float* p = enc + (size_t)b * P * ENC + d;
        float s = 0.f;
        #pragma unroll 8
        for (int pp = 0; pp < P; pp++) s += p[pp * ENC];
        sm[d] = s * (1.f / (float)P);
    }
    __syncthreads();
    int n = threadIdx.x;
    float ah = b_inh[n], ac = b_inc[n];
    #pragma unroll 8
    for (int k = 0; k < ENC; k++) {
        float m = sm[k];
        ah = fmaf(m, W_inh[k*HID + n], ah);
        ac = fmaf(m, W_inc[k*HID + n], ac);
    }
    g_h0[b*HID + n] = ah;
    g_cbuf[0][b*HID + n] = ac;
}

__global__ void __launch_bounds__(256) k_att1T(const float* __restrict__ enc,
                                               const float* __restrict__ W_ea,
                                               const float* __restrict__ b_ea) {
    __shared__ __align__(16) float sx[16 * ENC];
    int row0 = blockIdx.x * 16;
    for (int idx = threadIdx.x; idx < 16 * ENC; idx += blockDim.x)
        sx[idx] = enc[(size_t)row0 * ENC + idx];
    __syncthreads();
    int a = threadIdx.x;
    float acc[16];
    float bias = b_ea[a];
    #pragma unroll
    for (int r = 0; r < 16; r++) acc[r] = bias;
    #pragma unroll 2
    for (int k = 0; k < ENC; k += 4) {
        float w0 = W_ea[k*ATT + a];
        float w1 = W_ea[(k+1)*ATT + a];
        float w2 = W_ea[(k+2)*ATT + a];
        float w3 = W_ea[(k+3)*ATT + a];
        #pragma unroll
        for (int r = 0; r < 16; r++) {
            float4 xv = *(const float4*)&sx[r*ENC + k];
            acc[r] = fmaf(xv.x, w0, acc[r]);
            acc[r] = fmaf(xv.y, w1, acc[r]);
            acc[r] = fmaf(xv.z, w2, acc[r]);
            acc[r] = fmaf(xv.w, w3, acc[r]);
        }
    }
    #pragma unroll
    for (int r = 0; r < 16; r++) {
        int gr = row0 + r;
        int b = gr / P, p = gr - b * P;
        g_att1T[((size_t)b*ATT + a)*P + p] = acc[r];
    }
}

__global__ void __launch_bounds__(256) k_xproj(const int* __restrict__ captions,
                                               const float* __restrict__ emb,
                                               const float* __restrict__ W_ih,
                                               const float* __restrict__ b_ih,
                                               const float* __restrict__ b_hh) {
    __shared__ __align__(16) float sx[16 * EMB];
    int row0 = blockIdx.y * 16;
    for (int idx = threadIdx.x; idx < 16 * EMB; idx += blockDim.x) {
        int r = idx >> 9, k = idx & 511;
        int gr = row0 + r;
        int t = gr >> 5, b = gr & 31;
        int tok = captions[b*SLEN + t];
        sx[idx] = emb[(size_t)tok * EMB + k];
    }
    __syncthreads();
    int n = blockIdx.x * 256 + threadIdx.x;
    float acc[16];
    float bias = b_ih[n] + b_hh[n];
    #pragma unroll
    for (int r = 0; r < 16; r++) acc[r] = bias;
    #pragma unroll 2
    for (int k = 0; k < EMB; k += 4) {
        float w0 = W_ih[(size_t)k*N4H + n];
        float w1 = W_ih[(size_t)(k+1)*N4H + n];
        float w2 = W_ih[(size_t)(k+2)*N4H + n];
        float w3 = W_ih[(size_t)(k+3)*N4H + n];
        #pragma unroll
        for (int r = 0; r < 16; r++) {
            float4 xv = *(const float4*)&sx[r*EMB + k];
            acc[r] = fmaf(xv.x, w0, acc[r]);
            acc[r] = fmaf(xv.y, w1, acc[r]);
            acc[r] = fmaf(xv.z, w2, acc[r]);
            acc[r] = fmaf(xv.w, w3, acc[r]);
        }
    }
    #pragma unroll
    for (int r = 0; r < 16; r++)
        g_Xproj[(size_t)(row0 + r)*N4H + n] = acc[r];
}

// ---------------- persistent fused recurrent loop (R8 version, frozen) ----------------
#define SMEM_LOOP_FLOATS 55168
#define SMEM_LOOP_BYTES  (SMEM_LOOP_FLOATS * 4)

__global__ void __launch_bounds__(NTHR) k_loop(const float* __restrict__ enc,
                                               const float* __restrict__ w_fa,
                                               const float* __restrict__ b_fa,
                                               const float* __restrict__ W_ih,
                                               const float* __restrict__ W_da,
                                               const float* __restrict__ W_fb,
                                               const float* __restrict__ W_hh,
                                               const float* __restrict__ b_da,
                                               const float* __restrict__ b_fb) {
    extern __shared__ float smx[];
    float* sW   = smx;
    float* sWi  = smx + 12416;
    float* sbuf = smx + 24832;
    float* sAtt = smx + 53536;
    float* sbc  = smx + 54560;
    float* sg   = smx + 54592;

    int tid  = threadIdx.x;
    int cta  = blockIdx.x;
    int lane = tid & 31, warp = tid >> 5;
    int rg = lane & 7, ks = lane >> 3;

    {
        int cb24 = cta * 24;
        for (int e = tid; e < 512 * 24; e += NTHR) {
            int k = e / 24, c = e - k * 24;
            int n = cb24 + c;
            float v;
            if (n < ATT)            v = W_da[k*ATT + n];
            else if (n < ATT+ENC)   v = W_fb[k*ENC + (n - ATT)];
            else                    v = W_hh[k*N4H + (n - ATT - ENC)];
            sW[k*24 + c + 40*(k >> 7)] = v;
        }
        for (int e = tid; e < 768 * 16; e += NTHR) {
            int k = e >> 4, c = e & 15;
            int gc = (c >> 2) * 512 + cta * 4 + (c & 3);
            sWi[k*16 + c + 40*(k / 192)] = W_ih[(size_t)(EMB + k)*N4H + gc];
        }
        if (tid < 24) {
            int n = cta * 24 + tid;
            sbc[tid] = (n < ATT) ? b_da[n] : ((n < ATT+ENC) ? b_fb[n - ATT] : 0.f);
        }
    }
    __syncthreads();

    int bs = 0;
    for (int t = 0; t < T; t++) {
        // ===== Phase A =====
        {
            const float* hsrc = (t == 0) ? g_h0 : (g_H + (size_t)(t-1)*B*HID);
            #pragma unroll 4
            for (int r = 0; r < 32; r++) {
                int k0 = tid, k1 = tid + 256;
                sbuf[r*STRA + k0 + 40*(k0 >> 7)] = hsrc[r*512 + k0];
                sbuf[r*STRA + k1 + 40*(k1 >> 7)] = hsrc[r*512 + k1];
            }
            __syncthreads();
            float acc[12];
            #pragma unroll
            for (int x = 0; x < 12; x++) acc[x] = 0.f;
            int c0 = warp * 3;
            const float* hb = sbuf + 128*ks + 40*ks;
            const float* wb = sW + (128*ks)*24 + c0 + 40*ks;
            #pragma unroll 4
            for (int kl = 0; kl < 128; kl++) {
                float w0 = wb[kl*24 + 0];
                float w1 = wb[kl*24 + 1];
                float w2 = wb[kl*24 + 2];
                #pragma unroll
                for (int i = 0; i < 4; i++) {
                    float h = hb[(rg + 8*i)*STRA + kl];
                    acc[i*3+0] = fmaf(h, w0, acc[i*3+0]);
                    acc[i*3+1] = fmaf(h, w1, acc[i*3+1]);
                    acc[i*3+2] = fmaf(h, w2, acc[i*3+2]);
                }
            }
            #pragma unroll
            for (int x = 0; x < 12; x++) {
                acc[x] += __shfl_xor_sync(0xffffffffu, acc[x], 8);
                acc[x] += __shfl_xor_sync(0xffffffffu, acc[x], 16);
            }
            if (ks == 0) {
                #pragma unroll
                for (int i = 0; i < 4; i++) {
                    int row = rg + 8*i;
                    #pragma unroll
                    for (int j = 0; j < 3; j++)
                        g_y[row*NCAT + cta*24 + c0 + j] = acc[i*3+j] + sbc[c0 + j];
                }
            }
            __syncthreads();
        }
        gbar(bs); bs ^= 1;

        // ===== Phase B =====
        if (cta < 32) {
            int b = cta;
            float* s_att2  = sAtt;
            float* s_wfa   = sAtt + 256;
            float* s_red   = sAtt + 512;
            float* s_alpha = sAtt + 768;
            s_att2[tid] = g_y[b*NCAT + tid];
            s_wfa[tid]  = w_fa[tid];
            __syncthreads();

            float ev = -1e30f;
            if (tid < P) {
                float a0 = b_fa[0];
                const float* at = g_att1T + (size_t)(b*ATT)*P + tid;
                #pragma unroll 16
                for (int a = 0; a < ATT; a++) {
                    float v = at[(size_t)a*P] + s_att2[a];
                    a0 = fmaf(fmaxf(v, 0.f), s_wfa[a], a0);
                }
                ev = a0;
            }
            s_red[tid] = ev; __syncthreads();
            for (int s = 128; s > 0; s >>= 1) {
                if (tid < s) s_red[tid] = fmaxf(s_red[tid], s_red[tid + s]);
                __syncthreads();
            }
            float mx = s_red[0];
            __syncthreads();
            float ex = (tid < P) ? __expf(ev - mx) : 0.f;
            s_red[tid] = ex; __syncthreads();
            for (int s = 128; s > 0; s >>= 1) {
                if (tid < s) s_red[tid] += s_red[tid + s];
                __syncthreads();
            }
            float inv = 1.f / s_red[0];
            s_alpha[tid] = ex * inv;
            __syncthreads();

            float a0 = 0.f, a1 = 0.f, a2 = 0.f;
            const float* ep = enc + (size_t)b * P * ENC + tid;
            #pragma unroll 4
            for (int p = 0; p < P; p++) {
                float al = s_alpha[p];
                const float* rowp = ep + (size_t)p * ENC;
                a0 = fmaf(al, rowp[0],   a0);
                a1 = fmaf(al, rowp[256], a1);
                a2 = fmaf(al, rowp[512], a2);
            }
            g_awe[b*ENC + tid]       = sigm(g_y[b*NCAT + ATT + tid])       * a0;
            g_awe[b*ENC + 256 + tid] = sigm(g_y[b*NCAT + ATT + 256 + tid]) * a1;
            g_awe[b*ENC + 512 + tid] = sigm(g_y[b*NCAT + ATT + 512 + tid]) * a2;
        }
        gbar(bs); bs ^= 1;

        // ===== Phase C+D =====
        {
            #pragma unroll 2
            for (int r = 0; r < 32; r++) {
                #pragma unroll
                for (int q = 0; q < 3; q++) {
                    int k = tid + q * 256;
                    sbuf[r*STRC + k + 40*(k / 192)] = g_awe[r*768 + k];
                }
            }
            __syncthreads();
            float acc[8];
            #pragma unroll
            for (int x = 0; x < 8; x++) acc[x] = 0.f;
            int c0 = warp * 2;
            const float* ab = sbuf + 192*ks + 40*ks;
            const float* wb = sWi + (192*ks)*16 + c0 + 40*ks;
            #pragma unroll 4
            for (int kl = 0; kl < 192; kl++) {
                float w0 = wb[kl*16 + 0];
                float w1 = wb[kl*16 + 1];
                #pragma unroll
                for (int i = 0; i < 4; i++) {
                    float a = ab[(rg + 8*i)*STRC + kl];
                    acc[i*2+0] = fmaf(a, w0, acc[i*2+0]);
                    acc[i*2+1] = fmaf(a, w1, acc[i*2+1]);
                }
            }
            #pragma unroll
            for (int x = 0; x < 8; x++) {
                acc[x] += __shfl_xor_sync(0xffffffffu, acc[x], 8);
                acc[x] += __shfl_xor_sync(0xffffffffu, acc[x], 16);
            }
            if (ks == 0) {
                #pragma unroll
                for (int i = 0; i < 4; i++) {
                    int row = rg + 8*i;
                    #pragma unroll
                    for (int j = 0; j < 2; j++) {
                        int lc = c0 + j;
                        int gc = (lc >> 2) * 512 + cta * 4 + (lc & 3);
                        sg[row*STRG + lc] = acc[i*2+j]
                            + g_Xproj[(size_t)(t*B + row)*N4H + gc]
                            + g_y[row*NCAT + 1024 + gc];
                    }
                }
            }
            __syncthreads();
            if (tid < 128) {
                int row = tid >> 2, off = tid & 3;
                int u = cta * 4 + off;
                float gi = sg[row*STRG + off];
                float gf = sg[row*STRG + 4 + off];
                float gg = sg[row*STRG + 8 + off];
                float go = sg[row*STRG + 12 + off];
                float cp = g_cbuf[t & 1][row*512 + u];
                float cn = sigm(gf) * cp + sigm(gi) * tanhf(gg);
                float hn = sigm(go) * tanhf(cn);
                g_cbuf[(t + 1) & 1][row*512 + u] = cn;
                g_H[(size_t)t * B * HID + row*512 + u] = hn;
            }
            __syncthreads();
        }
        gbar(bs); bs ^= 1;
    }
    // 3 barriers * 40 steps = 120 (even) -> replay-safe
}

// ---------------- bf16 split conversions ----------------
__global__ void k_convA() {
    int i = blockIdx.x * 256 + threadIdx.x;
    if (i >= NROWS * HID) return;
    int m = i >> 9, k = i & 511;
    float x = g_H[i];
    __nv_bfloat16 hb = __float2bfloat16(x);
    __nv_bfloat16 lb = __float2bfloat16(x - __bfloat162float(hb));
    __nv_bfloat16* row = g_Abf + (size_t)m * KSPLIT;
    row[k] = hb;
    row[512 + k] = lb;
    row[1024 + k] = hb;
}

__global__ void k_convB(const float* __restrict__ W_out) {
    __shared__ float tile[32][33];
    int n0 = blockIdx.x * 32;
    int k0 = blockIdx.y * 32;
    int tn = threadIdx.x & 31, tr = threadIdx.x >> 5;
    #pragma unroll
    for (int r = 0; r < 4; r++) {
        int k = k0 + tr + r * 8;
        tile[tr + r * 8][tn] = W_out[(size_t)k * VOCAB + n0 + tn];
    }
    __syncthreads();
    #pragma unroll
    for (int r = 0; r < 4; r++) {
        int n = n0 + tr + r * 8;
        float x = tile[tn][tr + r * 8];
        __nv_bfloat16 hb = __float2bfloat16(x);
        __nv_bfloat16 lb = __float2bfloat16(x - __bfloat162float(hb));
        __nv_bfloat16* row = g_Bbf + (size_t)n * KSPLIT;
        row[k0 + tn] = hb;
        row[512 + k0 + tn] = hb;
        row[1024 + k0 + tn] = lb;
    }
}

// ---------------- mma.sync output GEMM (R8 version, frozen) ----------------
#define NT 24             // k-tiles (1536/64)
#define STAGE_BYTES 32768 // A 16KB + B 16KB per stage

__device__ __forceinline__ void gemm_load_tile(uint32_t sA,
                                               const __nv_bfloat16* gA,
                                               const __nv_bfloat16* gB, int tid) {
    uint32_t sB = sA + 16384;
    #pragma unroll
    for (int i = 0; i < 4; i++) {
        int chunk = tid + i * 256;          // 0..1023
        int r = chunk >> 3, c = chunk & 7;
        CP_ASYNC16(sA + SW128(r * 128 + c * 16),
                   (const char*)gA + (size_t)r * KSPLIT * 2 + c * 16);
    }
    #pragma unroll
    for (int i = 0; i < 4; i++) {
        int chunk = tid + i * 256;
        int r = chunk >> 3, c = chunk & 7;
        CP_ASYNC16(sB + SW128(r * 128 + c * 16),
                   (const char*)gB + (size_t)r * KSPLIT * 2 + c * 16);
    }
}

__global__ void __launch_bounds__(256) k_out_mma(const float* __restrict__ b_out,
                                                 float* __restrict__ out) {
    extern __shared__ char dsm[];
    uint32_t raw = smem_u32(dsm);
    uint32_t base = (raw + 1023) & ~1023u;

    int tid = threadIdx.x;
    int lane = tid & 31, wid = tid >> 5;
    int wm = wid & 1;
    int wn = wid >> 1;

    int row0 = blockIdx.x * 128;
    int n0   = blockIdx.y * 128;

    const __nv_bfloat16* gA0 = g_Abf + (size_t)row0 * KSPLIT;
    const __nv_bfloat16* gB0 = g_Bbf + (size_t)n0 * KSPLIT;

    int rowA = wm * 64 + (lane & 15);
    int koffA = (lane >> 4) << 4;
    int rowB = wn * 32 + (lane & 7) + ((lane >> 4) << 3);
    int koffB = ((lane >> 3) & 1) << 4;

    float acc[4][4][4];
    #pragma unroll
    for (int f = 0; f < 4; f++)
        #pragma unroll
        for (int j = 0; j < 4; j++)
            #pragma unroll
            for (int e = 0; e < 4; e++) acc[f][j][e] = 0.f;

    #pragma unroll
    for (int kt = 0; kt < 3; kt++) {
        gemm_load_tile(base + kt * STAGE_BYTES, gA0 + kt * 64, gB0 + kt * 64, tid);
        CP_COMMIT();
    }

    for (int kt = 0; kt < NT; kt++) {
        CP_WAIT2();
        __syncthreads();
        uint32_t sA = base + (kt % 3) * STAGE_BYTES;
        uint32_t sB = sA + 16384;
        #pragma unroll
        for (int kss = 0; kss < 4; kss++) {
            uint32_t a[4][4];
            #pragma unroll
            for (int f = 0; f < 4; f++)
                LDSM_X4(a[f][0], a[f][1], a[f][2], a[f][3],
                        sA + SW128((rowA + f * 16) * 128 + kss * 32 + koffA));
            uint32_t bfr[2][4];
            #pragma unroll
            for (int g = 0; g < 2; g++)
                LDSM_X4(bfr[g][0], bfr[g][1], bfr[g][2], bfr[g][3],
                        sB + SW128((rowB + g * 16) * 128 + kss * 32 + koffB));
            #pragma unroll
            for (int f = 0; f < 4; f++)
                #pragma unroll
                for (int j = 0; j < 4; j++)
                    MMA16816(acc[f][j], a[f],
                             bfr[j >> 1][(j & 1) * 2], bfr[j >> 1][(j & 1) * 2 + 1]);
        }
        __syncthreads();
        if (kt + 3 < NT) {
            gemm_load_tile(sA, gA0 + (size_t)(kt + 3) * 64, gB0 + (size_t)(kt + 3) * 64, tid);
            CP_COMMIT();
        }
    }
    CP_WAIT0();

    #pragma unroll
    for (int j = 0; j < 4; j++) {
        int n = n0 + wn * 32 + j * 8 + (lane & 3) * 2;
        float bo0 = b_out[n], bo1 = b_out[n + 1];
        #pragma unroll
        for (int f = 0; f < 4; f++) {
            int rl = wm * 64 + f * 16 + (lane >> 2);
            #pragma unroll
            for (int half = 0; half < 2; half++) {
                int grow = row0 + rl + half * 8;
                int bb = grow & 31, tt = grow >> 5;
                float2 v = make_float2(acc[f][j][half * 2] + bo0,
                                       acc[f][j][half * 2 + 1] + bo1);
                *(float2*)(out + ((size_t)bb * T + tt) * VOCAB + n) = v;
            }
        }
    }
}

// ---------------- launch: graph-level fork/join concurrency ----------------
extern "C" void kernel_launch(void* const* d_in, const int* in_sizes, int n_in,
                              void* d_out, int out_size) {
    const float* enc    = (const float*)d_in[0];
    const int*   caps   = (const int*)  d_in[1];
    const float* emb    = (const float*)d_in[2];
    const float* W_ea   = (const float*)d_in[3];
    const float* b_ea   = (const float*)d_in[4];
    const float* W_da   = (const float*)d_in[5];
    const float* b_da   = (const float*)d_in[6];
    const float* w_fa   = (const float*)d_in[7];
    const float* b_fa   = (const float*)d_in[8];
    const float* W_inh  = (const float*)d_in[9];
    const float* b_inh  = (const float*)d_in[10];
    const float* W_inc  = (const float*)d_in[11];
    const float* b_inc  = (const float*)d_in[12];
    const float* W_fb   = (const float*)d_in[13];
    const float* b_fb   = (const float*)d_in[14];
    const float* W_ih   = (const float*)d_in[15];
    const float* b_ih   = (const float*)d_in[16];
    const float* W_hh   = (const float*)d_in[17];
    const float* b_hh   = (const float*)d_in[18];
    const float* W_out  = (const float*)d_in[19];
    const float* b_out  = (const float*)d_in[20];
    float* out = (float*)d_out;

    cudaFuncSetAttribute(k_out_mma, cudaFuncAttributeMaxDynamicSharedMemorySize,
                         3 * STAGE_BYTES + 1024);
    cudaFuncSetAttribute(k_loop, cudaFuncAttributeMaxDynamicSharedMemorySize,
                         SMEM_LOOP_BYTES);

    // side streams + events (host objects; created fresh per call — kernel_launch
    // host code runs only for correctness + capture, replays don't re-execute it)
    cudaStream_t s1, s2, s3;
    cudaStreamCreateWithFlags(&s1, cudaStreamNonBlocking);
    cudaStreamCreateWithFlags(&s2, cudaStreamNonBlocking);
    cudaStreamCreateWithFlags(&s3, cudaStreamNonBlocking);
    cudaEvent_t e0, e1, e2, e3;
    cudaEventCreateWithFlags(&e0, cudaEventDisableTiming);
    cudaEventCreateWithFlags(&e1, cudaEventDisableTiming);
    cudaEventCreateWithFlags(&e2, cudaEventDisableTiming);
    cudaEventCreateWithFlags(&e3, cudaEventDisableTiming);

    // fork from the (captured) default stream
    cudaEventRecord(e0, 0);
    cudaStreamWaitEvent(s1, e0, 0);
    cudaStreamWaitEvent(s2, e0, 0);
    cudaStreamWaitEvent(s3, e0, 0);

    k_init<<<B, 512>>>(enc, W_inh, b_inh, W_inc, b_inc);                       // main
    k_att1T<<<(B*P)/16, 256, 0, s1>>>(enc, W_ea, b_ea);                        // s1
    k_xproj<<<dim3(N4H/256, NROWS/16), 256, 0, s2>>>(caps, emb, W_ih, b_ih, b_hh); // s2
    k_convB<<<dim3(VOCAB/32, HID/32), 256, 0, s3>>>(W_out);                    // s3 (hidden behind loop)

    // join s1, s2 before the recurrent loop
    cudaEventRecord(e1, s1);
    cudaEventRecord(e2, s2);
    cudaStreamWaitEvent(0, e1, 0);
    cudaStreamWaitEvent(0, e2, 0);

    k_loop<<<NCTA, NTHR, SMEM_LOOP_BYTES>>>(enc, w_fa, b_fa, W_ih,
                                            W_da, W_fb, W_hh, b_da, b_fb);
    k_convA<<<(NROWS*HID + 255)/256, 256>>>();

    // join s3 before the output GEMM
    cudaEventRecord(e3, s3);
    cudaStreamWaitEvent(0, e3, 0);

    k_out_mma<<<dim3(NROWS/128, VOCAB/128), 256, 3*STAGE_BYTES + 1024>>>(b_out, out);

    cudaEventDestroy(e0); cudaEventDestroy(e1);
    cudaEventDestroy(e2); cudaEventDestroy(e3);
    cudaStreamDestroy(s1); cudaStreamDestroy(s2); cudaStreamDestroy(s3);
}

// round 13
// speedup vs baseline: 1.0887x; 1.0354x over previous
#include <cuda_runtime.h>
#include <cuda_bf16.h>
#include <math.h>
#include <stdint.h>

// Problem constants
#define B    32
#define P    197
#define ENC  768
#define EMB  512
#define HID  512
#define ATT  256
#define VOCAB 32000
#define SLEN 41
#define T    40
#define N4H  2048          // 4*HID
#define NCAT 3072          // ATT + ENC + 4*HID
#define NROWS (T*B)        // 1280
#define KSPLIT 1536        // 3 * HID  (split-bf16 K)

#define NCTA 128
#define NTHR 256

// skewed staging strides (>= row footprint, ≡1 mod 32 for bank spread)
#define STRA 641
#define STRC 897
#define STRG 17            // gates staging stride

// ---------------- device scratch (no allocs allowed) ----------------
__device__ float g_h0[B*HID];
__device__ float g_cbuf[2][B*HID];
__device__ float g_att1T[B*ATT*P];      // [b][a][p]
__device__ float g_Xproj[NROWS*N4H];
__device__ float g_y[B*NCAT];
__device__ float g_awe[B*ENC];
__device__ float g_H[NROWS*HID];        // h rows, row = t*32 + b
__device__ __nv_bfloat16 g_Abf[NROWS*KSPLIT];         // [m][k'] = [Hh|Hl|Hh]
__device__ __nv_bfloat16 g_Bbf[(size_t)VOCAB*KSPLIT]; // [n][k'] = [Wh|Wh|Wl]

// global barrier state (zero-initialized; returns to this state every launch)
__device__ unsigned int g_cnt2[2];
__device__ volatile unsigned int g_flag2[2];

__device__ __forceinline__ float sigm(float x) { return 1.f / (1.f + __expf(-x)); }

__device__ __forceinline__ uint32_t smem_u32(const void* p) {
    uint32_t a;
    asm("{ .reg .u64 t; cvta.to.shared.u64 t, %1; cvt.u32.u64 %0, t; }" : "=r"(a) : "l"(p));
    return a;
}
#define SW128(off) ((off) ^ (((off) >> 3) & 0x70))

#define CP_ASYNC16(dst, src) asm volatile("cp.async.cg.shared.global [%0], [%1], 16;" :: "r"(dst), "l"(src))
#define CP_COMMIT()          asm volatile("cp.async.commit_group;" ::: "memory")
#define CP_WAIT2()           asm volatile("cp.async.wait_group 2;" ::: "memory")
#define CP_WAIT0()           asm volatile("cp.async.wait_group 0;" ::: "memory")

#define LDSM_X4(r0, r1, r2, r3, addr) \
    asm volatile("ldmatrix.sync.aligned.m8n8.x4.shared.b16 {%0,%1,%2,%3}, [%4];" \
        : "=r"(r0), "=r"(r1), "=r"(r2), "=r"(r3) : "r"(addr))

#define MMA16816(d, a, b0, b1) \
    asm volatile("mma.sync.aligned.m16n8k16.row.col.f32.bf16.bf16.f32 " \
        "{%0,%1,%2,%3}, {%4,%5,%6,%7}, {%8,%9}, {%0,%1,%2,%3};" \
        : "+f"((d)[0]), "+f"((d)[1]), "+f"((d)[2]), "+f"((d)[3]) \
        : "r"((a)[0]), "r"((a)[1]), "r"((a)[2]), "r"((a)[3]), "r"(b0), "r"(b1))

// grid-wide barrier (even count per launch -> replay-safe)
__device__ __forceinline__ void gbar(int slot) {
    __syncthreads();
    if (threadIdx.x == 0) {
        __threadfence();
        unsigned int old = atomicAdd(&g_cnt2[slot], 1u);
        if (old == NCTA - 1) {
            g_cnt2[slot] = 0;
            g_flag2[slot ^ 1] = 0;
            __threadfence();
            g_flag2[slot] = 1;
        } else {
            while (g_flag2[slot] == 0) { }
        }
        __threadfence();
    }
    __syncthreads();
}

// ---------------- setup kernels ----------------
__global__ void __launch_bounds__(512) k_init(const float* __restrict__ enc,
                                              const float* __restrict__ W_inh,
                                              const float* __restrict__ b_inh,
                                              const float* __restrict__ W_inc,
                                              const float* __restrict__ b_inc) {
    __shared__ float sm[ENC];
    int b = blockIdx.x;
    for (int d = threadIdx.x; d < ENC; d += 512) {
        const float* p = enc + (size_t)b * P * ENC + d;
        float s = 0.f;
        #pragma unroll 8
        for (int pp = 0; pp < P; pp++) s += p[pp * ENC];
        sm[d] = s * (1.f / (float)P);
    }
    __syncthreads();
    int n = threadIdx.x;
    float ah = b_inh[n], ac = b_inc[n];
    #pragma unroll 8
    for (int k = 0; k < ENC; k++) {
        float m = sm[k];
        ah = fmaf(m, W_inh[k*HID + n], ah);
        ac = fmaf(m, W_inc[k*HID + n], ac);
    }
    g_h0[b*HID + n] = ah;
    g_cbuf[0][b*HID + n] = ac;
}

__global__ void __launch_bounds__(256) k_att1T(const float* __restrict__ enc,
                                               const float* __restrict__ W_ea,
                                               const float* __restrict__ b_ea) {
    __shared__ __align__(16) float sx[16 * ENC];
    int row0 = blockIdx.x * 16;
    for (int idx = threadIdx.x; idx < 16 * ENC; idx += blockDim.x)
        sx[idx] = enc[(size_t)row0 * ENC + idx];
    __syncthreads();
    int a = threadIdx.x;
    float acc[16];
    float bias = b_ea[a];
    #pragma unroll
    for (int r = 0; r < 16; r++) acc[r] = bias;
    #pragma unroll 2
    for (int k = 0; k < ENC; k += 4) {
        float w0 = W_ea[k*ATT + a];
        float w1 = W_ea[(k+1)*ATT + a];
        float w2 = W_ea[(k+2)*ATT + a];
        float w3 = W_ea[(k+3)*ATT + a];
        #pragma unroll
        for (int r = 0; r < 16; r++) {
            float4 xv = *(const float4*)&sx[r*ENC + k];
            acc[r] = fmaf(xv.x, w0, acc[r]);
            acc[r] = fmaf(xv.y, w1, acc[r]);
            acc[r] = fmaf(xv.z, w2, acc[r]);
            acc[r] = fmaf(xv.w, w3, acc[r]);
        }
    }
    #pragma unroll
    for (int r = 0; r < 16; r++) {
        int gr = row0 + r;
        int b = gr / P, p = gr - b * P;
        g_att1T[((size_t)b*ATT + a)*P + p] = acc[r];
    }
}

__global__ void __launch_bounds__(256) k_xproj(const int* __restrict__ captions,
                                               const float* __restrict__ emb,
                                               const float* __restrict__ W_ih,
                                               const float* __restrict__ b_ih,
                                               const float* __restrict__ b_hh) {
    __shared__ __align__(16) float sx[16 * EMB];
    int row0 = blockIdx.y * 16;
    for (int idx = threadIdx.x; idx < 16 * EMB; idx += blockDim.x) {
        int r = idx >> 9, k = idx & 511;
        int gr = row0 + r;
        int t = gr >> 5, b = gr & 31;
        int tok = captions[b*SLEN + t];
        sx[idx] = emb[(size_t)tok * EMB + k];
    }
    __syncthreads();
    int n = blockIdx.x * 256 + threadIdx.x;
    float acc[16];
    float bias = b_ih[n] + b_hh[n];
    #pragma unroll
    for (int r = 0; r < 16; r++) acc[r] = bias;
    #pragma unroll 2
    for (int k = 0; k < EMB; k += 4) {
        float w0 = W_ih[(size_t)k*N4H + n];
        float w1 = W_ih[(size_t)(k+1)*N4H + n];
        float w2 = W_ih[(size_t)(k+2)*N4H + n];
        float w3 = W_ih[(size_t)(k+3)*N4H + n];
        #pragma unroll
        for (int r = 0; r < 16; r++) {
            float4 xv = *(const float4*)&sx[r*EMB + k];
            acc[r] = fmaf(xv.x, w0, acc[r]);
            acc[r] = fmaf(xv.y, w1, acc[r]);
            acc[r] = fmaf(xv.z, w2, acc[r]);
            acc[r] = fmaf(xv.w, w3, acc[r]);
        }
    }
    #pragma unroll
    for (int r = 0; r < 16; r++)
        g_Xproj[(size_t)(row0 + r)*N4H + n] = acc[r];
}

// ---------------- persistent fused recurrent loop (R8 version, frozen) ----------------
#define SMEM_LOOP_FLOATS 55168
#define SMEM_LOOP_BYTES  (SMEM_LOOP_FLOATS * 4)

__global__ void __launch_bounds__(NTHR) k_loop(const float* __restrict__ enc,
                                               const float* __restrict__ w_fa,
                                               const float* __restrict__ b_fa,
                                               const float* __restrict__ W_ih,
                                               const float* __restrict__ W_da,
                                               const float* __restrict__ W_fb,
                                               const float* __restrict__ W_hh,
                                               const float* __restrict__ b_da,
                                               const float* __restrict__ b_fb) {
    extern __shared__ float smx[];
    float* sW   = smx;
    float* sWi  = smx + 12416;
    float* sbuf = smx + 24832;
    float* sAtt = smx + 53536;
    float* sbc  = smx + 54560;
    float* sg   = smx + 54592;

    int tid  = threadIdx.x;
    int cta  = blockIdx.x;
    int lane = tid & 31, warp = tid >> 5;
    int rg = lane & 7, ks = lane >> 3;

    {
        int cb24 = cta * 24;
        for (int e = tid; e < 512 * 24; e += NTHR) {
            int k = e / 24, c = e - k * 24;
            int n = cb24 + c;
            float v;
            if (n < ATT)            v = W_da[k*ATT + n];
            else if (n < ATT+ENC)   v = W_fb[k*ENC + (n - ATT)];
            else                    v = W_hh[k*N4H + (n - ATT - ENC)];
            sW[k*24 + c + 40*(k >> 7)] = v;
        }
        for (int e = tid; e < 768 * 16; e += NTHR) {
            int k = e >> 4, c = e & 15;
            int gc = (c >> 2) * 512 + cta * 4 + (c & 3);
            sWi[k*16 + c + 40*(k / 192)] = W_ih[(size_t)(EMB + k)*N4H + gc];
        }
        if (tid < 24) {
            int n = cta * 24 + tid;
            sbc[tid] = (n < ATT) ? b_da[n] : ((n < ATT+ENC) ? b_fb[n - ATT] : 0.f);
        }
    }
    __syncthreads();

    int bs = 0;
    for (int t = 0; t < T; t++) {
        // ===== Phase A =====
        {
            const float* hsrc = (t == 0) ? g_h0 : (g_H + (size_t)(t-1)*B*HID);
            #pragma unroll 4
            for (int r = 0; r < 32; r++) {
                int k0 = tid, k1 = tid + 256;
                sbuf[r*STRA + k0 + 40*(k0 >> 7)] = hsrc[r*512 + k0];
                sbuf[r*STRA + k1 + 40*(k1 >> 7)] = hsrc[r*512 + k1];
            }
            __syncthreads();
            float acc[12];
            #pragma unroll
            for (int x = 0; x < 12; x++) acc[x] = 0.f;
            int c0 = warp * 3;
            const float* hb = sbuf + 128*ks + 40*ks;
            const float* wb = sW + (128*ks)*24 + c0 + 40*ks;
            #pragma unroll 4
            for (int kl = 0; kl < 128; kl++) {
                float w0 = wb[kl*24 + 0];
                float w1 = wb[kl*24 + 1];
                float w2 = wb[kl*24 + 2];
                #pragma unroll
                for (int i = 0; i < 4; i++) {
                    float h = hb[(rg + 8*i)*STRA + kl];
                    acc[i*3+0] = fmaf(h, w0, acc[i*3+0]);
                    acc[i*3+1] = fmaf(h, w1, acc[i*3+1]);
                    acc[i*3+2] = fmaf(h, w2, acc[i*3+2]);
                }
            }
            #pragma unroll
            for (int x = 0; x < 12; x++) {
                acc[x] += __shfl_xor_sync(0xffffffffu, acc[x], 8);
                acc[x] += __shfl_xor_sync(0xffffffffu, acc[x], 16);
            }
            if (ks == 0) {
                #pragma unroll
                for (int i = 0; i < 4; i++) {
                    int row = rg + 8*i;
                    #pragma unroll
                    for (int j = 0; j < 3; j++)
                        g_y[row*NCAT + cta*24 + c0 + j] = acc[i*3+j] + sbc[c0 + j];
                }
            }
            __syncthreads();
        }
        gbar(bs); bs ^= 1;

        // ===== Phase B =====
        if (cta < 32) {
            int b = cta;
            float* s_att2  = sAtt;
            float* s_wfa   = sAtt + 256;
            float* s_red   = sAtt + 512;
            float* s_alpha = sAtt + 768;
            s_att2[tid] = g_y[b*NCAT + tid];
            s_wfa[tid]  = w_fa[tid];
            __syncthreads();

            float ev = -1e30f;
            if (tid < P) {
                float a0 = b_fa[0];
                const float* at = g_att1T + (size_t)(b*ATT)*P + tid;
                #pragma unroll 16
                for (int a = 0; a < ATT; a++) {
                    float v = at[(size_t)a*P] + s_att2[a];
                    a0 = fmaf(fmaxf(v, 0.f), s_wfa[a], a0);
                }
                ev = a0;
            }
            s_red[tid] = ev; __syncthreads();
            for (int s = 128; s > 0; s >>= 1) {
                if (tid < s) s_red[tid] = fmaxf(s_red[tid], s_red[tid + s]);
                __syncthreads();
            }
            float mx = s_red[0];
            __syncthreads();
            float ex = (tid < P) ? __expf(ev - mx) : 0.f;
            s_red[tid] = ex; __syncthreads();
            for (int s = 128; s > 0; s >>= 1) {
                if (tid < s) s_red[tid] += s_red[tid + s];
                __syncthreads();
            }
            float inv = 1.f / s_red[0];
            s_alpha[tid] = ex * inv;
            __syncthreads();

            float a0 = 0.f, a1 = 0.f, a2 = 0.f;
            const float* ep = enc + (size_t)b * P * ENC + tid;
            #pragma unroll 4
            for (int p = 0; p < P; p++) {
                float al = s_alpha[p];
                const float* rowp = ep + (size_t)p * ENC;
                a0 = fmaf(al, rowp[0],   a0);
                a1 = fmaf(al, rowp[256], a1);
                a2 = fmaf(al, rowp[512], a2);
            }
            g_awe[b*ENC + tid]       = sigm(g_y[b*NCAT + ATT + tid])       * a0;
            g_awe[b*ENC + 256 + tid] = sigm(g_y[b*NCAT + ATT + 256 + tid]) * a1;
            g_awe[b*ENC + 512 + tid] = sigm(g_y[b*NCAT + ATT + 512 + tid]) * a2;
        }
        gbar(bs); bs ^= 1;

        // ===== Phase C+D =====
        {
            #pragma unroll 2
            for (int r = 0; r < 32; r++) {
                #pragma unroll
                for (int q = 0; q < 3; q++) {
                    int k = tid + q * 256;
                    sbuf[r*STRC + k + 40*(k / 192)] = g_awe[r*768 + k];
                }
            }
            __syncthreads();
            float acc[8];
            #pragma unroll
            for (int x = 0; x < 8; x++) acc[x] = 0.f;
            int c0 = warp * 2;
            const float* ab = sbuf + 192*ks + 40*ks;
            const float* wb = sWi + (192*ks)*16 + c0 + 40*ks;
            #pragma unroll 4
            for (int kl = 0; kl < 192; kl++) {
                float w0 = wb[kl*16 + 0];
                float w1 = wb[kl*16 + 1];
                #pragma unroll
                for (int i = 0; i < 4; i++) {
                    float a = ab[(rg + 8*i)*STRC + kl];
                    acc[i*2+0] = fmaf(a, w0, acc[i*2+0]);
                    acc[i*2+1] = fmaf(a, w1, acc[i*2+1]);
                }
            }
            #pragma unroll
            for (int x = 0; x < 8; x++) {
                acc[x] += __shfl_xor_sync(0xffffffffu, acc[x], 8);
                acc[x] += __shfl_xor_sync(0xffffffffu, acc[x], 16);
            }
            if (ks == 0) {
                #pragma unroll
                for (int i = 0; i < 4; i++) {
                    int row = rg + 8*i;
                    #pragma unroll
                    for (int j = 0; j < 2; j++) {
                        int lc = c0 + j;
                        int gc = (lc >> 2) * 512 + cta * 4 + (lc & 3);
                        sg[row*STRG + lc] = acc[i*2+j]
                            + g_Xproj[(size_t)(t*B + row)*N4H + gc]
                            + g_y[row*NCAT + 1024 + gc];
                    }
                }
            }
            __syncthreads();
            if (tid < 128) {
                int row = tid >> 2, off = tid & 3;
                int u = cta * 4 + off;
                float gi = sg[row*STRG + off];
                float gf = sg[row*STRG + 4 + off];
                float gg = sg[row*STRG + 8 + off];
                float go = sg[row*STRG + 12 + off];
                float cp = g_cbuf[t & 1][row*512 + u];
                float cn = sigm(gf) * cp + sigm(gi) * tanhf(gg);
                float hn = sigm(go) * tanhf(cn);
                g_cbuf[(t + 1) & 1][row*512 + u] = cn;
                g_H[(size_t)t * B * HID + row*512 + u] = hn;
            }
            __syncthreads();
        }
        gbar(bs); bs ^= 1;
    }
    // 3 barriers * 40 steps = 120 (even) -> replay-safe
}

// ---------------- bf16 split conversions ----------------
__global__ void k_convA() {
    int i = blockIdx.x * 256 + threadIdx.x;
    if (i >= NROWS * HID) return;
    int m = i >> 9, k = i & 511;
    float x = g_H[i];
    __nv_bfloat16 hb = __float2bfloat16(x);
    __nv_bfloat16 lb = __float2bfloat16(x - __bfloat162float(hb));
    __nv_bfloat16* row = g_Abf + (size_t)m * KSPLIT;
    row[k] = hb;
    row[512 + k] = lb;
    row[1024 + k] = hb;
}

__global__ void k_convB(const float* __restrict__ W_out) {
    __shared__ float tile[32][33];
    int n0 = blockIdx.x * 32;
    int k0 = blockIdx.y * 32;
    int tn = threadIdx.x & 31, tr = threadIdx.x >> 5;
    #pragma unroll
    for (int r = 0; r < 4; r++) {
        int k = k0 + tr + r * 8;
        tile[tr + r * 8][tn] = W_out[(size_t)k * VOCAB + n0 + tn];
    }
    __syncthreads();
    #pragma unroll
    for (int r = 0; r < 4; r++) {
        int n = n0 + tr + r * 8;
        float x = tile[tn][tr + r * 8];
        __nv_bfloat16 hb = __float2bfloat16(x);
        __nv_bfloat16 lb = __float2bfloat16(x - __bfloat162float(hb));
        __nv_bfloat16* row = g_Bbf + (size_t)n * KSPLIT;
        row[k0 + tn] = hb;
        row[512 + k0 + tn] = hb;
        row[1024 + k0 + tn] = lb;
    }
}

// ---------------- mma.sync output GEMM: CTA tile 128x256, warp tile 64x64 ----------------
#define NT 24               // k-tiles (1536/64)
#define STAGE_BYTES 49152   // A 16KB + B 32KB per stage

__device__ __forceinline__ void gemm_load_tile(uint32_t sA,
                                               const __nv_bfloat16* gA,
                                               const __nv_bfloat16* gB, int tid) {
    uint32_t sB = sA + 16384;
    #pragma unroll
    for (int i = 0; i < 4; i++) {
        int chunk = tid + i * 256;          // 0..1023 (A: 128 rows x 8)
        int r = chunk >> 3, c = chunk & 7;
        CP_ASYNC16(sA + SW128(r * 128 + c * 16),
                   (const char*)gA + (size_t)r * KSPLIT * 2 + c * 16);
    }
    #pragma unroll
    for (int i = 0; i < 8; i++) {
        int chunk = tid + i * 256;          // 0..2047 (B: 256 rows x 8)
        int r = chunk >> 3, c = chunk & 7;
        CP_ASYNC16(sB + SW128(r * 128 + c * 16),
                   (const char*)gB + (size_t)r * KSPLIT * 2 + c * 16);
    }
}

__global__ void __launch_bounds__(256) k_out_mma(const float* __restrict__ b_out,
                                                 float* __restrict__ out) {
    extern __shared__ char dsm[];
    uint32_t raw = smem_u32(dsm);
    uint32_t base = (raw + 1023) & ~1023u;

    int tid = threadIdx.x;
    int lane = tid & 31, wid = tid >> 5;
    int wm = wid & 1;        // m offset 64*wm
    int wn = wid >> 1;       // n offset 64*wn (0..3)

    int row0 = blockIdx.x * 128;   // grid.x = 10 (m fast -> B-tile L2 reuse)
    int n0   = blockIdx.y * 256;   // grid.y = 125

    const __nv_bfloat16* gA0 = g_Abf + (size_t)row0 * KSPLIT;
    const __nv_bfloat16* gB0 = g_Bbf + (size_t)n0 * KSPLIT;

    int rowA = wm * 64 + (lane & 15);
    int koffA = (lane >> 4) << 4;
    int rowB = wn * 64 + (lane & 7) + ((lane >> 4) << 3);
    int koffB = ((lane >> 3) & 1) << 4;

    float acc[4][8][4];
    #pragma unroll
    for (int f = 0; f < 4; f++)
        #pragma unroll
        for (int j = 0; j < 8; j++)
            #pragma unroll
            for (int e = 0; e < 4; e++) acc[f][j][e] = 0.f;

    #pragma unroll
    for (int kt = 0; kt < 3; kt++) {
        gemm_load_tile(base + kt * STAGE_BYTES, gA0 + kt * 64, gB0 + kt * 64, tid);
        CP_COMMIT();
    }

    for (int kt = 0; kt < NT; kt++) {
        CP_WAIT2();
        __syncthreads();
        uint32_t sA = base + (kt % 3) * STAGE_BYTES;
        uint32_t sB = sA + 16384;
        #pragma unroll
        for (int kss = 0; kss < 4; kss++) {
            uint32_t a[4][4];
            #pragma unroll
            for (int f = 0; f < 4; f++)
                LDSM_X4(a[f][0], a[f][1], a[f][2], a[f][3],
                        sA + SW128((rowA + f * 16) * 128 + kss * 32 + koffA));
            uint32_t bfr[4][4];
            #pragma unroll
            for (int g = 0; g < 4; g++)
                LDSM_X4(bfr[g][0], bfr[g][1], bfr[g][2], bfr[g][3],
                        sB + SW128((rowB + g * 16) * 128 + kss * 32 + koffB));
            #pragma unroll
            for (int f = 0; f < 4; f++)
                #pragma unroll
                for (int j = 0; j < 8; j++)
                    MMA16816(acc[f][j], a[f],
                             bfr[j >> 1][(j & 1) * 2], bfr[j >> 1][(j & 1) * 2 + 1]);
        }
        __syncthreads();
        if (kt + 3 < NT) {
            gemm_load_tile(sA, gA0 + (size_t)(kt + 3) * 64, gB0 + (size_t)(kt + 3) * 64, tid);
            CP_COMMIT();
        }
    }
    CP_WAIT0();

    #pragma unroll
    for (int j = 0; j < 8; j++) {
        int n = n0 + wn * 64 + j * 8 + (lane & 3) * 2;
        float bo0 = b_out[n], bo1 = b_out[n + 1];
        #pragma unroll
        for (int f = 0; f < 4; f++) {
            int rl = wm * 64 + f * 16 + (lane >> 2);
            #pragma unroll
            for (int half = 0; half < 2; half++) {
                int grow = row0 + rl + half * 8;
                int bb = grow & 31, tt = grow >> 5;
                float2 v = make_float2(acc[f][j][half * 2] + bo0,
                                       acc[f][j][half * 2 + 1] + bo1);
                *(float2*)(out + ((size_t)bb * T + tt) * VOCAB + n) = v;
            }
        }
    }
}

// ---------------- launch: graph-level fork/join concurrency ----------------
extern "C" void kernel_launch(void* const* d_in, const int* in_sizes, int n_in,
                              void* d_out, int out_size) {
    const float* enc    = (const float*)d_in[0];
    const int*   caps   = (const int*)  d_in[1];
    const float* emb    = (const float*)d_in[2];
    const float* W_ea   = (const float*)d_in[3];
    const float* b_ea   = (const float*)d_in[4];
    const float* W_da   = (const float*)d_in[5];
    const float* b_da   = (const float*)d_in[6];
    const float* w_fa   = (const float*)d_in[7];
    const float* b_fa   = (const float*)d_in[8];
    const float* W_inh  = (const float*)d_in[9];
    const float* b_inh  = (const float*)d_in[10];
    const float* W_inc  = (const float*)d_in[11];
    const float* b_inc  = (const float*)d_in[12];
    const float* W_fb   = (const float*)d_in[13];
    const float* b_fb   = (const float*)d_in[14];
    const float* W_ih   = (const float*)d_in[15];
    const float* b_ih   = (const float*)d_in[16];
    const float* W_hh   = (const float*)d_in[17];
    const float* b_hh   = (const float*)d_in[18];
    const float* W_out  = (const float*)d_in[19];
    const float* b_out  = (const float*)d_in[20];
    float* out = (float*)d_out;

    cudaFuncSetAttribute(k_out_mma, cudaFuncAttributeMaxDynamicSharedMemorySize,
                         3 * STAGE_BYTES + 1024);
    cudaFuncSetAttribute(k_loop, cudaFuncAttributeMaxDynamicSharedMemorySize,
                         SMEM_LOOP_BYTES);

    cudaStream_t s1, s2, s3;
    cudaStreamCreateWithFlags(&s1, cudaStreamNonBlocking);
    cudaStreamCreateWithFlags(&s2, cudaStreamNonBlocking);
    cudaStreamCreateWithFlags(&s3, cudaStreamNonBlocking);
    cudaEvent_t e0, e1, e2, e3;
    cudaEventCreateWithFlags(&e0, cudaEventDisableTiming);
    cudaEventCreateWithFlags(&e1, cudaEventDisableTiming);
    cudaEventCreateWithFlags(&e2, cudaEventDisableTiming);
    cudaEventCreateWithFlags(&e3, cudaEventDisableTiming);

    cudaEventRecord(e0, 0);
    cudaStreamWaitEvent(s1, e0, 0);
    cudaStreamWaitEvent(s2, e0, 0);
    cudaStreamWaitEvent(s3, e0, 0);

    k_init<<<B, 512>>>(enc, W_inh, b_inh, W_inc, b_inc);
    k_att1T<<<(B*P)/16, 256, 0, s1>>>(enc, W_ea, b_ea);
    k_xproj<<<dim3(N4H/256, NROWS/16), 256, 0, s2>>>(caps, emb, W_ih, b_ih, b_hh);
    k_convB<<<dim3(VOCAB/32, HID/32), 256, 0, s3>>>(W_out);

    cudaEventRecord(e1, s1);
    cudaEventRecord(e2, s2);
    cudaStreamWaitEvent(0, e1, 0);
    cudaStreamWaitEvent(0, e2, 0);

    k_loop<<<NCTA, NTHR, SMEM_LOOP_BYTES>>>(enc, w_fa, b_fa, W_ih,
                                            W_da, W_fb, W_hh, b_da, b_fb);
    k_convA<<<(NROWS*HID + 255)/256, 256>>>();

    cudaEventRecord(e3, s3);
    cudaStreamWaitEvent(0, e3, 0);

    k_out_mma<<<dim3(NROWS/128, VOCAB/256), 256, 3*STAGE_BYTES + 1024>>>(b_out, out);

    cudaEventDestroy(e0); cudaEventDestroy(e1);
    cudaEventDestroy(e2); cudaEventDestroy(e3);
    cudaStreamDestroy(s1); cudaStreamDestroy(s2); cudaStreamDestroy(s3);
}